// round 15
// baseline (speedup 1.0000x reference)
#include <cuda_runtime.h>

#define Bn 4
#define Tn 512
#define Cn 8
#define Fn 257
#define BFn (Bn*Fn)            // 1028
#define Dn 40
#define TPn 505                // T - delay - taps + 1
#define NBTCF (Bn*Tn*Cn*Fn)    // 4210688

typedef unsigned long long u64;

// Workspaces (no allocation allowed)
__device__ float2 g_Y[(size_t)BFn * Tn * Cn];   // (b,f,t,c) complex
__device__ float2 g_w2[(size_t)BFn * Tn];       // (1/p, 1/p) packed weights
__device__ float2 g_E[(size_t)BFn * Cn * Tn];   // enhanced, (b,f,c,t)

// ---- packed f32x2 helpers -------------------------------------------------
__device__ __forceinline__ u64 pk(float lo, float hi) {
    u64 r; asm("mov.b64 %0,{%1,%2};" : "=l"(r) : "f"(lo), "f"(hi)); return r;
}
__device__ __forceinline__ u64 rep(float x) { return pk(x, x); }
__device__ __forceinline__ void upk(u64 v, float& lo, float& hi) {
    asm("mov.b64 {%0,%1},%2;" : "=f"(lo), "=f"(hi) : "l"(v));
}
__device__ __forceinline__ u64 f2fma(u64 a, u64 b, u64 c) {
    u64 d; asm("fma.rn.f32x2 %0,%1,%2,%3;" : "=l"(d) : "l"(a), "l"(b), "l"(c)); return d;
}
__device__ __forceinline__ u64 f2mul(u64 a, u64 b) {
    u64 d; asm("mul.rn.f32x2 %0,%1,%2;" : "=l"(d) : "l"(a), "l"(b)); return d;
}
__device__ __forceinline__ u64 f2neg(u64 a) {
    u64 d; asm("xor.b64 %0,%1,0x8000000080000000;" : "=l"(d) : "l"(a)); return d;
}

// ---------------------------------------------------------------------------
// Kernel 1: pack (B,T,C,F) re/im -> (b,f,t,c) float2, power + packed weights
// ---------------------------------------------------------------------------
__global__ __launch_bounds__(256) void k_prep(const float* __restrict__ re,
                                              const float* __restrict__ im,
                                              float* __restrict__ outP) {
    __shared__ float sRe[32][65];
    __shared__ float sIm[32][65];
    __shared__ float sP[32][9];
    int b  = blockIdx.z;
    int f0 = blockIdx.y * 32;
    int t0 = blockIdx.x * 8;
    int tid = threadIdx.x;
    int fl = tid & 31, g = tid >> 5;
    int f = f0 + fl;
    float acc = 0.f;
    if (f < Fn) {
        const float* pr = re + ((size_t)((b * Tn + t0 + g) * Cn)) * Fn + f;
        const float* pi = im + ((size_t)((b * Tn + t0 + g) * Cn)) * Fn + f;
        #pragma unroll
        for (int c = 0; c < 8; c++) {
            float rr = pr[c * Fn], ii = pi[c * Fn];
            sRe[fl][g * 8 + c] = rr;
            sIm[fl][g * 8 + c] = ii;
            acc += rr * rr + ii * ii;
        }
    }
    sP[fl][g] = fmaxf(acc * 0.125f, 1e-6f);
    __syncthreads();

    int fl3 = tid >> 3, tl3 = tid & 7;
    int f3 = f0 + fl3;
    if (f3 < Fn) {
        float pv = sP[fl3][tl3];
        int pidx = (b * Fn + f3) * Tn + t0 + tl3;
        outP[pidx] = pv;
        float wv = 1.0f / pv;
        g_w2[pidx] = make_float2(wv, wv);
        float rr[8], ii[8];
        #pragma unroll
        for (int c = 0; c < 8; c++) {
            rr[c] = sRe[fl3][tl3 * 8 + c];
            ii[c] = sIm[fl3][tl3 * 8 + c];
        }
        float2* dst = g_Y + ((size_t)(b * Fn + f3) * Tn + t0) * Cn + tl3 * 8;
        #pragma unroll
        for (int q = 0; q < 4; q++)
            *(float4*)(dst + q * 2) = make_float4(rr[2*q], ii[2*q], rr[2*q+1], ii[2*q+1]);
    }
}

// ---------------------------------------------------------------------------
// Kernel 2: fused per-(b,f) WPE. 1028 blocks, 256 threads, 3 blocks/SM.
// Phase-1 tile map is warp-uniform in t: warps {0,1}/{3,4}/{6,7} cover
// tiles 0-63 at phases 0/1/2; tiles 64-74 on warp 2 (ph0 lanes 0-10,
// ph2 lanes 16-26) and warp 5 (ph1 lanes 0-10). Kills the mid-warp phase
// straddle that doubled LDS wavefronts on 2 of 8 warps.
// ---------------------------------------------------------------------------
__global__ __launch_bounds__(256, 3) void k_wpe() {
    const int bf  = blockIdx.x;
    const int tid = threadIdx.x;

    // shared layout:
    //  [0,16384)       sYre plane [t*8+c]
    //  [16384,32768)   sYim plane
    //  [32768,36864)   sw2 packed weights (aliases sM head; dead at deposit)
    //  [32768,48128)   sM 40x48 complex
    //  [43008,48128)   sG packed u64 G pairs (after GJ; sM dead)
    //  [0,33088)       sYt c-major [c*517+t] (tail; planes dead)
    //  [48128,48768)   scol double buffer (u64[2][40]); head doubles as eps
    //  [48768,49152)   prow (u64[48])
    __shared__ __align__(16) char s_raw[49152];
    float*  sYre = (float*)s_raw;
    float*  sYim = (float*)(s_raw + 16384);
    float2* sw2  = (float2*)(s_raw + 32768);
    float2* sM   = (float2*)(s_raw + 32768);
    u64*    sG   = (u64*)(s_raw + 43008);
    u64*    scol2= (u64*)(s_raw + 48128);
    u64*    prow = (u64*)(s_raw + 48768);
    float*  sEps = (float*)(s_raw + 48128);
    float2* sYt  = (float2*)s_raw;

    // ---------------- load planes + weights --------------------------------
    {
        const float2* Yg = g_Y + (size_t)bf * (Tn * Cn);
        #pragma unroll
        for (int q = 0; q < 16; q++) {
            int idx = tid + q * 256;
            float2 v = Yg[idx];
            sYre[idx] = v.x; sYim[idx] = v.y;
        }
        for (int idx = tid; idx < Tn; idx += 256)
            sw2[idx] = g_w2[(size_t)bf * Tn + idx];
    }
    __syncthreads();

    // ---------------- Phase 1: warp-uniform tile/phase map ------------------
    int wid = tid >> 5, lane = tid & 31;
    int ph, tile; bool act1;
    if (wid == 2) {
        bool lo = lane < 11;
        bool hi = (lane >= 16 && lane < 27);
        act1 = lo || hi;
        ph = lo ? 0 : 2;
        tile = act1 ? (64 + (lo ? lane : lane - 16)) : 0;
    } else if (wid == 5) {
        act1 = lane < 11;
        ph = 1;
        tile = act1 ? (64 + lane) : 0;
    } else {
        act1 = true;
        ph = (wid >= 6) ? 2 : (wid >= 3 ? 1 : 0);
        int wsub = wid - ph * 3;       // 0 or 1
        tile = wsub * 32 + lane;       // 0..63
    }
    int it = 0, r2 = tile;
    while (r2 >= 12 - it) { r2 -= 12 - it; it++; }
    int jt = it + r2;
    int aOff = (4 - (it >> 1)) * 8 + (it & 1) * 4;
    int bOff = (jt >= 10) ? (7 * 8 + (jt - 10) * 4)
                          : ((4 - (jt >> 1)) * 8 + (jt & 1) * 4);

    u64 accR[2][4], accI[2][4];
    #pragma unroll
    for (int rp = 0; rp < 2; rp++)
        #pragma unroll
        for (int s = 0; s < 4; s++) { accR[rp][s] = 0ull; accI[rp][s] = 0ull; }

    if (act1) {
        #pragma unroll 2
        for (int t = ph; t < TPn; t += 3) {
            u64 wp = *(const u64*)(sw2 + t + 7);
            ulonglong2 aX = *(const ulonglong2*)(sYre + t * 8 + aOff);
            ulonglong2 aY = *(const ulonglong2*)(sYim + t * 8 + aOff);
            u64 axw0  = f2mul(aX.x, wp), axw1  = f2mul(aX.y, wp);
            u64 ayw0  = f2mul(aY.x, wp), ayw1  = f2mul(aY.y, wp);
            u64 aywn0 = f2neg(ayw0),     aywn1 = f2neg(ayw1);   // ALU pipe
            float4 bxv = *(const float4*)(sYre + t * 8 + bOff);
            float4 byv = *(const float4*)(sYim + t * 8 + bOff);
            float bx[4] = {bxv.x, bxv.y, bxv.z, bxv.w};
            float by[4] = {byv.x, byv.y, byv.z, byv.w};
            #pragma unroll
            for (int s = 0; s < 4; s++) {
                u64 Bx = rep(bx[s]), By = rep(by[s]);
                accR[0][s] = f2fma(axw0, Bx, f2fma(ayw0,  By, accR[0][s]));
                accR[1][s] = f2fma(axw1, Bx, f2fma(ayw1,  By, accR[1][s]));
                accI[0][s] = f2fma(axw0, By, f2fma(aywn0, Bx, accI[0][s]));
                accI[1][s] = f2fma(axw1, By, f2fma(aywn1, Bx, accI[1][s]));
            }
        }
    }
    __syncthreads();   // planes/sw2 reads done before sM deposit

    float fR[4][4], fI[4][4];
    #pragma unroll
    for (int rp = 0; rp < 2; rp++)
        #pragma unroll
        for (int s = 0; s < 4; s++) {
            upk(accR[rp][s], fR[2 * rp][s], fR[2 * rp + 1][s]);
            upk(accI[rp][s], fI[2 * rp][s], fI[2 * rp + 1][s]);
        }

    // deposit rounds keyed by ph: 0 = init, 1 = add, 2 = add + mirror
    if (act1 && ph == 0) {
        #pragma unroll
        for (int r = 0; r < 4; r++)
            #pragma unroll
            for (int s = 0; s < 4; s++)
                sM[(it * 4 + r) * 48 + jt * 4 + s] = make_float2(fR[r][s], fI[r][s]);
    }
    __syncthreads();
    if (act1 && ph == 1) {
        #pragma unroll
        for (int r = 0; r < 4; r++)
            #pragma unroll
            for (int s = 0; s < 4; s++) {
                int idx = (it * 4 + r) * 48 + jt * 4 + s;
                float2 v = sM[idx];
                v.x += fR[r][s]; v.y += fI[r][s];
                sM[idx] = v;
            }
    }
    __syncthreads();
    if (act1 && ph == 2) {
        #pragma unroll
        for (int r = 0; r < 4; r++)
            #pragma unroll
            for (int s = 0; s < 4; s++) {
                int i = it * 4 + r, j = jt * 4 + s;
                float2 v = sM[i * 48 + j];
                v.x += fR[r][s]; v.y += fI[r][s];
                sM[i * 48 + j] = v;
                if (jt < 10 && jt > it)
                    sM[j * 48 + i] = make_float2(v.x, -v.y);
            }
    }
    __syncthreads();

    // ---------------- diag loading -----------------------------------------
    if (tid == 0) {
        float tr = 0.f;
        for (int i = 0; i < Dn; i++) tr += sM[i * 48 + i].x;
        *sEps = 1e-10f * tr / (float)Dn;
    }
    __syncthreads();
    float epsv = *sEps;
    __syncthreads();
    if (tid < Dn) sM[tid * 48 + tid].x += epsv;
    __syncthreads();

    // ---------------- Gauss-Jordan on [R | P], rows in registers -----------
    const bool act = tid < 240;
    const int  gi  = tid / 6;            // row 0..39
    const int  j0  = (tid % 6) * 8;      // chunk start col
    u64 row[8];
    if (act) {
        #pragma unroll
        for (int j = 0; j < 8; j++)
            row[j] = *(const u64*)&sM[gi * 48 + j0 + j];
    }
    if (act && j0 == 0) scol2[gi] = row[0];
    __syncthreads();

    for (int k = 0; k < Dn; k++) {
        u64* scur = scol2 + (k & 1) * 40;
        u64* snxt = scol2 + ((k + 1) & 1) * 40;
        if (act && gi == k) {
            float akr, aki; upk(scur[k], akr, aki);
            (void)aki;
            u64 ip = rep(1.0f / akr);
            #pragma unroll
            for (int j = 0; j < 8; j++) {
                row[j] = f2mul(row[j], ip);
                prow[j0 + j] = row[j];
            }
        }
        __syncthreads();
        if (act && gi != k) {
            float fr, fi2; upk(scur[gi], fr, fi2);
            u64 fA = pk(-fr, -fr), fB = pk(fi2, -fi2);
            #pragma unroll
            for (int j = 0; j < 8; j++) {
                u64 pA = prow[j0 + j];
                float pr_, pi_; upk(pA, pr_, pi_);
                u64 pB = pk(pi_, pr_);
                row[j] = f2fma(fA, pA, f2fma(fB, pB, row[j]));
            }
        }
        if (act && k < Dn - 1 && (unsigned)(k + 1 - j0) < 8u)
            snxt[gi] = row[k + 1 - j0];
        __syncthreads();
    }

    // ---------------- pack G (u64 pairs) to smem, rebuild Y c-major --------
    if (act && j0 == 40) {
        #pragma unroll
        for (int e = 0; e < 8; e++) {
            float gr, gi2; upk(row[e], gr, gi2);
            sG[(gi * 8 + e) * 2]     = pk(-gr, -gr);
            sG[(gi * 8 + e) * 2 + 1] = pk(gi2, -gi2);
        }
    }
    float tR[16], tI[16];
    #pragma unroll
    for (int q = 0; q < 16; q++) {
        int idx = tid + q * 256;
        tR[q] = sYre[idx]; tI[q] = sYim[idx];
    }
    __syncthreads();
    #pragma unroll
    for (int q = 0; q < 16; q++) {
        int idx = tid + q * 256;
        sYt[(idx & 7) * 517 + (idx >> 3)] = make_float2(tR[q], tI[q]);
    }
    __syncthreads();

    // ---------------- tail: 2 t's per thread, packed-G inner loop ----------
    float2* gEp = g_E + (size_t)bf * (Cn * Tn);
    {
        int ta = 2 * tid;          // even t
        u64 oA[8], oB[8];
        #pragma unroll
        for (int e = 0; e < 8; e++) {
            oA[e] = *(const u64*)&sYt[e * 517 + ta];
            oB[e] = *(const u64*)&sYt[e * 517 + ta + 1];
        }
        #pragma unroll 1
        for (int tau = 0; tau < 5; tau++) {
            int tsa = ta - 3 - tau;          // [-7, 504]
            int tsb = tsa + 1;
            #pragma unroll
            for (int d = 0; d < 8; d++) {
                int i = tau * 8 + d;
                u64 yAa = 0ull, yBa = 0ull, yAb = 0ull, yBb = 0ull;
                if (tsa >= 0) {
                    yAa = *(const u64*)&sYt[d * 517 + tsa];
                    float yr, yi; upk(yAa, yr, yi);
                    yBa = pk(yi, yr);
                }
                if (tsb >= 0) {
                    yAb = *(const u64*)&sYt[d * 517 + tsb];
                    float yr, yi; upk(yAb, yr, yi);
                    yBb = pk(yi, yr);
                }
                const u64* gp = sG + i * 16;
                #pragma unroll
                for (int e = 0; e < 8; e++) {
                    ulonglong2 g = *(const ulonglong2*)(gp + 2 * e);
                    oA[e] = f2fma(g.x, yAa, f2fma(g.y, yBa, oA[e]));
                    oB[e] = f2fma(g.x, yAb, f2fma(g.y, yBb, oB[e]));
                }
            }
        }
        #pragma unroll
        for (int e = 0; e < 8; e++) {
            float ar_, ai_, br_, bi_;
            upk(oA[e], ar_, ai_);
            upk(oB[e], br_, bi_);
            *(float4*)&gEp[e * Tn + ta] = make_float4(ar_, ai_, br_, bi_);
        }
    }
}

// ---------------------------------------------------------------------------
// Kernel 3: (b,f,c,t) -> (B,T,C,F) re/im with ilens mask
// ---------------------------------------------------------------------------
__global__ __launch_bounds__(256) void k_out(float* __restrict__ outRe,
                                             float* __restrict__ outIm,
                                             const int* __restrict__ ilens) {
    __shared__ float tRe[32][33];
    __shared__ float tIm[32][33];
    int b  = blockIdx.z;
    int t0 = blockIdx.y * 32;
    int f0 = blockIdx.x * 32;
    int len = ilens[b];
    int tid = threadIdx.x;
    int l32 = tid & 31, q = tid >> 5;

    for (int c = 0; c < 8; c++) {
        __syncthreads();
        for (int fr = q; fr < 32; fr += 8) {
            int f = f0 + fr;
            int t = t0 + l32;
            if (f < Fn) {
                float2 v = g_E[((size_t)(b * Fn + f) * 8 + c) * Tn + t];
                tRe[fr][l32] = v.x;
                tIm[fr][l32] = v.y;
            }
        }
        __syncthreads();
        for (int tr = q; tr < 32; tr += 8) {
            int t = t0 + tr;
            int f = f0 + l32;
            if (f < Fn) {
                float vr = tRe[l32][tr];
                float vi = tIm[l32][tr];
                if (t >= len) { vr = 0.f; vi = 0.f; }
                size_t o = ((size_t)(b * Tn + t) * 8 + c) * Fn + f;
                outRe[o] = vr;
                outIm[o] = vi;
            }
        }
    }
}

// ---------------------------------------------------------------------------
extern "C" void kernel_launch(void* const* d_in, const int* in_sizes, int n_in,
                              void* d_out, int out_size) {
    const float* re = (const float*)d_in[0];
    const float* im = (const float*)d_in[1];
    const int* ilens = (const int*)d_in[2];
    float* outRe = (float*)d_out;
    float* outIm = outRe + (size_t)NBTCF;
    float* outP  = outRe + (size_t)2 * NBTCF;

    k_prep<<<dim3(Tn / 8, 9, Bn), 256>>>(re, im, outP);
    k_wpe<<<BFn, 256>>>();
    k_out<<<dim3((Fn + 31) / 32, Tn / 32, Bn), 256>>>(outRe, outIm, ilens);
}

// round 16
// speedup vs baseline: 1.0208x; 1.0208x over previous
#include <cuda_runtime.h>

#define Bn 4
#define Tn 512
#define Cn 8
#define Fn 257
#define BFn (Bn*Fn)            // 1028
#define Dn 40
#define TPn 505                // T - delay - taps + 1
#define NBTCF (Bn*Tn*Cn*Fn)    // 4210688

typedef unsigned long long u64;

// Workspaces (no allocation allowed)
__device__ float2 g_Y[(size_t)BFn * Tn * Cn];   // (b,f,t,c) complex
__device__ float2 g_w2[(size_t)BFn * Tn];       // (1/p, 1/p) packed weights
__device__ float2 g_E[(size_t)BFn * Cn * Tn];   // enhanced, (b,f,c,t)

// ---- packed f32x2 helpers -------------------------------------------------
__device__ __forceinline__ u64 pk(float lo, float hi) {
    u64 r; asm("mov.b64 %0,{%1,%2};" : "=l"(r) : "f"(lo), "f"(hi)); return r;
}
__device__ __forceinline__ u64 rep(float x) { return pk(x, x); }
__device__ __forceinline__ void upk(u64 v, float& lo, float& hi) {
    asm("mov.b64 {%0,%1},%2;" : "=f"(lo), "=f"(hi) : "l"(v));
}
__device__ __forceinline__ u64 f2fma(u64 a, u64 b, u64 c) {
    u64 d; asm("fma.rn.f32x2 %0,%1,%2,%3;" : "=l"(d) : "l"(a), "l"(b), "l"(c)); return d;
}
__device__ __forceinline__ u64 f2mul(u64 a, u64 b) {
    u64 d; asm("mul.rn.f32x2 %0,%1,%2;" : "=l"(d) : "l"(a), "l"(b)); return d;
}
__device__ __forceinline__ u64 f2neg(u64 a) {
    u64 d; asm("xor.b64 %0,%1,0x8000000080000000;" : "=l"(d) : "l"(a)); return d;
}

// ---------------------------------------------------------------------------
// Kernel 1: pack (B,T,C,F) re/im -> (b,f,t,c) float2, power + packed weights
// ---------------------------------------------------------------------------
__global__ __launch_bounds__(256) void k_prep(const float* __restrict__ re,
                                              const float* __restrict__ im,
                                              float* __restrict__ outP) {
    __shared__ float sRe[32][65];
    __shared__ float sIm[32][65];
    __shared__ float sP[32][9];
    int b  = blockIdx.z;
    int f0 = blockIdx.y * 32;
    int t0 = blockIdx.x * 8;
    int tid = threadIdx.x;
    int fl = tid & 31, g = tid >> 5;
    int f = f0 + fl;
    float acc = 0.f;
    if (f < Fn) {
        const float* pr = re + ((size_t)((b * Tn + t0 + g) * Cn)) * Fn + f;
        const float* pi = im + ((size_t)((b * Tn + t0 + g) * Cn)) * Fn + f;
        #pragma unroll
        for (int c = 0; c < 8; c++) {
            float rr = pr[c * Fn], ii = pi[c * Fn];
            sRe[fl][g * 8 + c] = rr;
            sIm[fl][g * 8 + c] = ii;
            acc += rr * rr + ii * ii;
        }
    }
    sP[fl][g] = fmaxf(acc * 0.125f, 1e-6f);
    __syncthreads();

    int fl3 = tid >> 3, tl3 = tid & 7;
    int f3 = f0 + fl3;
    if (f3 < Fn) {
        float pv = sP[fl3][tl3];
        int pidx = (b * Fn + f3) * Tn + t0 + tl3;
        outP[pidx] = pv;
        float wv = 1.0f / pv;
        g_w2[pidx] = make_float2(wv, wv);
        float rr[8], ii[8];
        #pragma unroll
        for (int c = 0; c < 8; c++) {
            rr[c] = sRe[fl3][tl3 * 8 + c];
            ii[c] = sIm[fl3][tl3 * 8 + c];
        }
        float2* dst = g_Y + ((size_t)(b * Fn + f3) * Tn + t0) * Cn + tl3 * 8;
        #pragma unroll
        for (int q = 0; q < 4; q++)
            *(float4*)(dst + q * 2) = make_float4(rr[2*q], ii[2*q], rr[2*q+1], ii[2*q+1]);
    }
}

// ---------------------------------------------------------------------------
// Kernel 2: fused per-(b,f) WPE. 1028 blocks, 256 threads, 3 blocks/SM.
// (Byte-equivalent to the best-measured round-7 configuration.)
// ---------------------------------------------------------------------------
__global__ __launch_bounds__(256, 3) void k_wpe() {
    const int bf  = blockIdx.x;
    const int tid = threadIdx.x;

    __shared__ __align__(16) char s_raw[49152];
    float*  sYre = (float*)s_raw;
    float*  sYim = (float*)(s_raw + 16384);
    float2* sw2  = (float2*)(s_raw + 32768);
    float2* sM   = (float2*)(s_raw + 32768);
    float4* gpAB = (float4*)(s_raw + 43008);
    u64*    scol2= (u64*)(s_raw + 48128);
    u64*    prow = (u64*)(s_raw + 48768);
    float*  sEps = (float*)(s_raw + 48128);
    float2* sYt  = (float2*)s_raw;

    // ---------------- load planes + weights --------------------------------
    {
        const float2* Yg = g_Y + (size_t)bf * (Tn * Cn);
        #pragma unroll
        for (int q = 0; q < 16; q++) {
            int idx = tid + q * 256;
            float2 v = Yg[idx];
            sYre[idx] = v.x; sYim[idx] = v.y;
        }
        for (int idx = tid; idx < Tn; idx += 256)
            sw2[idx] = g_w2[(size_t)bf * Tn + idx];
    }
    __syncthreads();

    // ---------------- Phase 1: 75 4x4 tiles, 3 t-phases --------------------
    int tile = tid % 75;
    int ph   = tid / 75;      // 0,1,2 active; 3 idle
    int it = 0, r2 = tile;
    while (r2 >= 12 - it) { r2 -= 12 - it; it++; }
    int jt = it + r2;
    int aOff = (4 - (it >> 1)) * 8 + (it & 1) * 4;
    int bOff = (jt >= 10) ? (7 * 8 + (jt - 10) * 4)
                          : ((4 - (jt >> 1)) * 8 + (jt & 1) * 4);

    u64 accR[2][4], accI[2][4];
    #pragma unroll
    for (int rp = 0; rp < 2; rp++)
        #pragma unroll
        for (int s = 0; s < 4; s++) { accR[rp][s] = 0ull; accI[rp][s] = 0ull; }

    if (ph < 3) {
        #pragma unroll 2
        for (int t = ph; t < TPn; t += 3) {
            u64 wp = *(const u64*)(sw2 + t + 7);
            ulonglong2 aX = *(const ulonglong2*)(sYre + t * 8 + aOff);
            ulonglong2 aY = *(const ulonglong2*)(sYim + t * 8 + aOff);
            u64 axw0  = f2mul(aX.x, wp), axw1  = f2mul(aX.y, wp);
            u64 ayw0  = f2mul(aY.x, wp), ayw1  = f2mul(aY.y, wp);
            u64 aywn0 = f2neg(ayw0),     aywn1 = f2neg(ayw1);   // ALU pipe
            float4 bxv = *(const float4*)(sYre + t * 8 + bOff);
            float4 byv = *(const float4*)(sYim + t * 8 + bOff);
            float bx[4] = {bxv.x, bxv.y, bxv.z, bxv.w};
            float by[4] = {byv.x, byv.y, byv.z, byv.w};
            #pragma unroll
            for (int s = 0; s < 4; s++) {
                u64 Bx = rep(bx[s]), By = rep(by[s]);
                accR[0][s] = f2fma(axw0, Bx, f2fma(ayw0,  By, accR[0][s]));
                accR[1][s] = f2fma(axw1, Bx, f2fma(ayw1,  By, accR[1][s]));
                accI[0][s] = f2fma(axw0, By, f2fma(aywn0, Bx, accI[0][s]));
                accI[1][s] = f2fma(axw1, By, f2fma(aywn1, Bx, accI[1][s]));
            }
        }
    }
    __syncthreads();   // planes/sw2 reads done before sM deposit

    float fR[4][4], fI[4][4];
    #pragma unroll
    for (int rp = 0; rp < 2; rp++)
        #pragma unroll
        for (int s = 0; s < 4; s++) {
            upk(accR[rp][s], fR[2 * rp][s], fR[2 * rp + 1][s]);
            upk(accI[rp][s], fI[2 * rp][s], fI[2 * rp + 1][s]);
        }

    if (ph == 1) {
        #pragma unroll
        for (int r = 0; r < 4; r++)
            #pragma unroll
            for (int s = 0; s < 4; s++)
                sM[(it * 4 + r) * 48 + jt * 4 + s] = make_float2(fR[r][s], fI[r][s]);
    }
    __syncthreads();
    if (ph == 2) {
        #pragma unroll
        for (int r = 0; r < 4; r++)
            #pragma unroll
            for (int s = 0; s < 4; s++) {
                int idx = (it * 4 + r) * 48 + jt * 4 + s;
                float2 v = sM[idx];
                v.x += fR[r][s]; v.y += fI[r][s];
                sM[idx] = v;
            }
    }
    __syncthreads();
    if (ph == 0) {
        #pragma unroll
        for (int r = 0; r < 4; r++)
            #pragma unroll
            for (int s = 0; s < 4; s++) {
                int i = it * 4 + r, j = jt * 4 + s;
                float2 v = sM[i * 48 + j];
                v.x += fR[r][s]; v.y += fI[r][s];
                sM[i * 48 + j] = v;
                if (jt < 10 && jt > it)
                    sM[j * 48 + i] = make_float2(v.x, -v.y);
            }
    }
    __syncthreads();

    // ---------------- diag loading -----------------------------------------
    if (tid == 0) {
        float tr = 0.f;
        for (int i = 0; i < Dn; i++) tr += sM[i * 48 + i].x;
        *sEps = 1e-10f * tr / (float)Dn;
    }
    __syncthreads();
    float epsv = *sEps;
    __syncthreads();
    if (tid < Dn) sM[tid * 48 + tid].x += epsv;
    __syncthreads();

    // ---------------- Gauss-Jordan on [R | P], rows in registers -----------
    const bool act = tid < 240;
    const int  gi  = tid / 6;            // row 0..39
    const int  j0  = (tid % 6) * 8;      // chunk start col
    u64 row[8];
    if (act) {
        #pragma unroll
        for (int j = 0; j < 8; j++)
            row[j] = *(const u64*)&sM[gi * 48 + j0 + j];
    }
    if (act && j0 == 0) scol2[gi] = row[0];
    __syncthreads();

    for (int k = 0; k < Dn; k++) {
        u64* scur = scol2 + (k & 1) * 40;
        u64* snxt = scol2 + ((k + 1) & 1) * 40;
        if (act && gi == k) {
            float akr, aki; upk(scur[k], akr, aki);
            (void)aki;
            u64 ip = rep(1.0f / akr);
            #pragma unroll
            for (int j = 0; j < 8; j++) {
                row[j] = f2mul(row[j], ip);
                prow[j0 + j] = row[j];
            }
        }
        __syncthreads();
        if (act && gi != k) {
            float fr, fi2; upk(scur[gi], fr, fi2);
            u64 fA = pk(-fr, -fr), fB = pk(fi2, -fi2);
            #pragma unroll
            for (int j = 0; j < 8; j++) {
                u64 pA = prow[j0 + j];
                float pr_, pi_; upk(pA, pr_, pi_);
                u64 pB = pk(pi_, pr_);
                row[j] = f2fma(fA, pA, f2fma(fB, pB, row[j]));
            }
        }
        if (act && k < Dn - 1 && (unsigned)(k + 1 - j0) < 8u)
            snxt[gi] = row[k + 1 - j0];
        __syncthreads();
    }

    // ---------------- pack G for tail, rebuild Y c-major -------------------
    if (act && j0 == 40) {
        #pragma unroll
        for (int e = 0; e < 8; e++) {
            float gr, gi2; upk(row[e], gr, gi2);
            gpAB[gi * 8 + e] = make_float4(-gr, -gr, gi2, -gi2);
        }
    }
    float tR[16], tI[16];
    #pragma unroll
    for (int q = 0; q < 16; q++) {
        int idx = tid + q * 256;
        tR[q] = sYre[idx]; tI[q] = sYim[idx];
    }
    __syncthreads();
    #pragma unroll
    for (int q = 0; q < 16; q++) {
        int idx = tid + q * 256;
        sYt[(idx & 7) * 517 + (idx >> 3)] = make_float2(tR[q], tI[q]);
    }
    __syncthreads();

    // ---------------- tail: 2 t's per thread, single pass ------------------
    float2* gEp = g_E + (size_t)bf * (Cn * Tn);
    {
        int ta = 2 * tid;          // even t
        u64 oA[8], oB[8];
        #pragma unroll
        for (int e = 0; e < 8; e++) {
            oA[e] = *(const u64*)&sYt[e * 517 + ta];
            oB[e] = *(const u64*)&sYt[e * 517 + ta + 1];
        }
        #pragma unroll 1
        for (int tau = 0; tau < 5; tau++) {
            int tsa = ta - 3 - tau;          // [-7, 504]
            int tsb = tsa + 1;
            #pragma unroll
            for (int d = 0; d < 8; d++) {
                int i = tau * 8 + d;
                u64 yAa = 0ull, yBa = 0ull, yAb = 0ull, yBb = 0ull;
                if (tsa >= 0) {
                    yAa = *(const u64*)&sYt[d * 517 + tsa];
                    float yr, yi; upk(yAa, yr, yi);
                    yBa = pk(yi, yr);
                }
                if (tsb >= 0) {
                    yAb = *(const u64*)&sYt[d * 517 + tsb];
                    float yr, yi; upk(yAb, yr, yi);
                    yBb = pk(yi, yr);
                }
                #pragma unroll
                for (int e = 0; e < 8; e++) {
                    float4 gv = gpAB[i * 8 + e];
                    u64 gA = pk(gv.x, gv.y);
                    u64 gB = pk(gv.z, gv.w);
                    oA[e] = f2fma(gA, yAa, f2fma(gB, yBa, oA[e]));
                    oB[e] = f2fma(gA, yAb, f2fma(gB, yBb, oB[e]));
                }
            }
        }
        #pragma unroll
        for (int e = 0; e < 8; e++) {
            float ar_, ai_, br_, bi_;
            upk(oA[e], ar_, ai_);
            upk(oB[e], br_, bi_);
            *(float4*)&gEp[e * Tn + ta] = make_float4(ar_, ai_, br_, bi_);
        }
    }
}

// ---------------------------------------------------------------------------
// Kernel 3: (b,f,c,t) -> (B,T,C,F) re/im with ilens mask.
// 2 channels per barrier round: 8 syncthreads instead of 16.
// ---------------------------------------------------------------------------
__global__ __launch_bounds__(256) void k_out(float* __restrict__ outRe,
                                             float* __restrict__ outIm,
                                             const int* __restrict__ ilens) {
    __shared__ float tRe0[32][33];
    __shared__ float tIm0[32][33];
    __shared__ float tRe1[32][33];
    __shared__ float tIm1[32][33];
    int b  = blockIdx.z;
    int t0 = blockIdx.y * 32;
    int f0 = blockIdx.x * 32;
    int len = ilens[b];
    int tid = threadIdx.x;
    int l32 = tid & 31, q = tid >> 5;

    for (int c = 0; c < 8; c += 2) {
        __syncthreads();
        for (int fr = q; fr < 32; fr += 8) {
            int f = f0 + fr;
            int t = t0 + l32;
            if (f < Fn) {
                const float2* base = g_E + ((size_t)(b * Fn + f) * 8 + c) * Tn;
                float2 v0 = base[t];
                float2 v1 = base[Tn + t];
                tRe0[fr][l32] = v0.x;
                tIm0[fr][l32] = v0.y;
                tRe1[fr][l32] = v1.x;
                tIm1[fr][l32] = v1.y;
            }
        }
        __syncthreads();
        for (int tr = q; tr < 32; tr += 8) {
            int t = t0 + tr;
            int f = f0 + l32;
            if (f < Fn) {
                float vr0 = tRe0[l32][tr], vi0 = tIm0[l32][tr];
                float vr1 = tRe1[l32][tr], vi1 = tIm1[l32][tr];
                if (t >= len) { vr0 = vi0 = vr1 = vi1 = 0.f; }
                size_t o = ((size_t)(b * Tn + t) * 8 + c) * Fn + f;
                outRe[o]      = vr0;
                outIm[o]      = vi0;
                outRe[o + Fn] = vr1;
                outIm[o + Fn] = vi1;
            }
        }
    }
}

// ---------------------------------------------------------------------------
extern "C" void kernel_launch(void* const* d_in, const int* in_sizes, int n_in,
                              void* d_out, int out_size) {
    const float* re = (const float*)d_in[0];
    const float* im = (const float*)d_in[1];
    const int* ilens = (const int*)d_in[2];
    float* outRe = (float*)d_out;
    float* outIm = outRe + (size_t)NBTCF;
    float* outP  = outRe + (size_t)2 * NBTCF;

    k_prep<<<dim3(Tn / 8, 9, Bn), 256>>>(re, im, outP);
    k_wpe<<<BFn, 256>>>();
    k_out<<<dim3((Fn + 31) / 32, Tn / 32, Bn), 256>>>(outRe, outIm, ilens);
}